// round 4
// baseline (speedup 1.0000x reference)
#include <cuda_runtime.h>
#include <cuda_bf16.h>
#include <math.h>
#include <stdint.h>

// Problem constants
#define NPOS   3
#define BSZ    2048
#define DN     128
#define NN     8192
#define XROWS  (NPOS*BSZ)
#define LOG2E10  14.426950408889634f   // 10 / ln(2)

#define NTILES 4                       // 128-wide column tiles per CTA strip
#define TILE_BYTES 16384               // 128 rows x 128 fp8
#define SMEM_BYTES 49152               // A + 2xB

// Scratch (device globals — no allocation allowed)
__device__ uint8_t g_bZ[NN * DN];      // unit rows, e4m3
__device__ float g_sumexp[NN];
__device__ float g_posp[512];
__device__ float g_lsum;
__device__ int   g_cnt[64];

// ---------------------------------------------------------------- helpers
__device__ __forceinline__ uint32_t s2u(const void* p) {
    uint32_t a;
    asm("{ .reg .u64 t; cvta.to.shared.u64 t, %1; cvt.u32.u64 %0, t; }" : "=r"(a) : "l"(p));
    return a;
}
__device__ __forceinline__ float ex2(float x) {
    float y; asm("ex2.approx.ftz.f32 %0, %1;" : "=f"(y) : "f"(x)); return y;
}
__device__ __forceinline__ float lg2(float x) {
    float y; asm("lg2.approx.f32 %0, %1;" : "=f"(y) : "f"(x)); return y;
}
__device__ __forceinline__ uint16_t cvt8x2(float a, float b) {
    uint16_t r;
    asm("cvt.rn.satfinite.e4m3x2.f32 %0, %1, %2;" : "=h"(r) : "f"(a), "f"(b));
    return r;
}
__device__ __forceinline__ void ldmx4(uint32_t& r0, uint32_t& r1, uint32_t& r2,
                                      uint32_t& r3, uint32_t a) {
    asm volatile("ldmatrix.sync.aligned.m8n8.x4.shared.b16 {%0,%1,%2,%3}, [%4];"
                 : "=r"(r0), "=r"(r1), "=r"(r2), "=r"(r3) : "r"(a));
}
__device__ __forceinline__ void mmafp8(float* d, uint32_t a0, uint32_t a1,
                                       uint32_t a2, uint32_t a3,
                                       uint32_t b0, uint32_t b1) {
    asm volatile(
        "mma.sync.aligned.m16n8k32.row.col.f32.e4m3.e4m3.f32 "
        "{%0,%1,%2,%3},{%4,%5,%6,%7},{%8,%9},{%0,%1,%2,%3};"
        : "+f"(d[0]), "+f"(d[1]), "+f"(d[2]), "+f"(d[3])
        : "r"(a0), "r"(a1), "r"(a2), "r"(a3), "r"(b0), "r"(b1));
}

// Load one 128x128-fp8 tile into smem, XOR-swizzled: row*128B, 16B chunk c
// stored at (c ^ (r&7)). Conflict-free for ldmatrix reads.
__device__ __forceinline__ void load_tile(uint32_t sdst, const uint8_t* src,
                                          int row0, int tid) {
#pragma unroll
    for (int i = 0; i < 4; i++) {
        int idx = i * 256 + tid;          // 1024 chunks of 16B
        int r = idx >> 3;
        int c = idx & 7;
        uint32_t off = (uint32_t)r * 128u + (uint32_t)((c ^ (r & 7)) << 4);
        const char* g = (const char*)(src + (size_t)(row0 + r) * DN) + (c << 4);
        asm volatile("cp.async.cg.shared.global [%0], [%1], 16;"
                     :: "r"(sdst + off), "l"(g));
    }
}

// ---------------------------------------------------------------------------
// Kernel 1 (fused prep): blocks 0..1023 normalize rows -> e4m3; blocks
// 1024..1087 compute positive-term partials from raw fp32 inputs.
// Also zeroes accumulators used by LATER kernels.
// ---------------------------------------------------------------------------
__global__ void kprep(const float* __restrict__ x, const float* __restrict__ xp)
{
    int tid  = threadIdx.x;
    int wid  = tid >> 5;
    int lane = tid & 31;
    int gid  = blockIdx.x * 256 + tid;

    if (gid < NN) g_sumexp[gid] = 0.0f;
    if (gid < 64) g_cnt[gid] = 0;
    if (gid == 64) g_lsum = 0.0f;

    if (blockIdx.x < 1024) {
        int row = gid >> 5;
        const float* src = (row < XROWS) ? (x + (size_t)row * DN)
                                         : (xp + (size_t)(row - XROWS) * DN);
        float4 v = ((const float4*)src)[lane];
        float ss = v.x*v.x + v.y*v.y + v.z*v.z + v.w*v.w;
#pragma unroll
        for (int o = 16; o; o >>= 1) ss += __shfl_xor_sync(0xffffffffu, ss, o);
        float r = rsqrtf(ss);
        uint32_t lo = cvt8x2(v.y * r, v.x * r);
        uint32_t hi = cvt8x2(v.w * r, v.z * r);
        ((uint32_t*)g_bZ)[row * 32 + lane] = (hi << 16) | lo;
    } else {
        int pw = (blockIdx.x - 1024) * 8 + wid;   // 0..511
        float acc = 0.0f;
#pragma unroll
        for (int u = 0; u < 4; u++) {
            int b = pw * 4 + u;
            float4 p = ((const float4*)(xp + (size_t)b * DN))[lane];
            float ssp = p.x*p.x + p.y*p.y + p.z*p.z + p.w*p.w;
#pragma unroll
            for (int o = 16; o; o >>= 1) ssp += __shfl_xor_sync(0xffffffffu, ssp, o);
            float rp = rsqrtf(ssp);
#pragma unroll
            for (int q = 0; q < NPOS; q++) {
                float4 a = ((const float4*)(x + (size_t)(q * BSZ + b) * DN))[lane];
                float ssx = a.x*a.x + a.y*a.y + a.z*a.z + a.w*a.w;
                float dt  = a.x*p.x + a.y*p.y + a.z*p.z + a.w*p.w;
#pragma unroll
                for (int o = 16; o; o >>= 1) {
                    ssx += __shfl_xor_sync(0xffffffffu, ssx, o);
                    dt  += __shfl_xor_sync(0xffffffffu, dt,  o);
                }
                acc += dt * rsqrtf(ssx) * rp;
            }
        }
        if (lane == 0) g_posp[pw] = acc;
    }
}

// ---------------------------------------------------------------------------
// Kernel 2: fp8 MMA fused GEMM + exp row-accumulate + (last CTA per row
// block) log reduction. CTA: 128 rows x 512 cols. grid (16, 64), 256 thr.
// ---------------------------------------------------------------------------
__global__ void __launch_bounds__(256, 2) kmain()
{
    extern __shared__ char smc[];
    __shared__ float red[128];
    __shared__ int s_old;
    uint32_t sb = s2u(smc);
    uint32_t Ab = sb;
    uint32_t Bb = sb + (uint32_t)TILE_BYTES;

    int tid  = threadIdx.x;
    int wid  = tid >> 5;
    int lane = tid & 31;
    int rm0   = blockIdx.y * 128;
    int cbase = blockIdx.x * (NTILES * 128);

    int wm = (wid & 1) * 64;
    int wn = (wid >> 1) * 32;
    int rr = lane & 15;
    int ch = lane >> 4;

    load_tile(Ab, g_bZ, rm0, tid);
    load_tile(Bb, g_bZ, cbase, tid);
    asm volatile("cp.async.commit_group;");

    uint32_t aoff[4]; uint32_t a7[4];
#pragma unroll
    for (int mi = 0; mi < 4; mi++) {
        int row = wm + mi * 16 + rr;
        aoff[mi] = Ab + (uint32_t)row * 128u;
        a7[mi]   = (uint32_t)(row & 7);
    }
    uint32_t boff[2]; uint32_t b7[2];
#pragma unroll
    for (int np = 0; np < 2; np++) {
        int row = wn + np * 16 + rr;
        boff[np] = (uint32_t)row * 128u;
        b7[np]   = (uint32_t)(row & 7);
    }

    float rowsum[8];
#pragma unroll
    for (int i = 0; i < 8; i++) rowsum[i] = 0.0f;

    int tq = lane >> 2;
    int tc = (lane & 3) * 2;

    for (int t = 0; t < NTILES; t++) {
        int buf = t & 1;
        __syncthreads();
        if (t + 1 < NTILES) {
            load_tile(Bb + (uint32_t)(buf ^ 1) * TILE_BYTES, g_bZ,
                      cbase + (t + 1) * 128, tid);
            asm volatile("cp.async.commit_group;");
            asm volatile("cp.async.wait_group 1;" ::: "memory");
        } else {
            asm volatile("cp.async.wait_group 0;" ::: "memory");
        }
        __syncthreads();

        uint32_t Bbase = Bb + (uint32_t)buf * TILE_BYTES;

        float acc[4][4][4];
#pragma unroll
        for (int mi = 0; mi < 4; mi++)
#pragma unroll
            for (int ni = 0; ni < 4; ni++)
#pragma unroll
                for (int e = 0; e < 4; e++) acc[mi][ni][e] = 0.0f;

#pragma unroll
        for (int ks = 0; ks < 4; ks++) {
            uint32_t c0 = (uint32_t)(ks * 2 + ch);
            uint32_t b[2][4];
#pragma unroll
            for (int np = 0; np < 2; np++)
                ldmx4(b[np][0], b[np][1], b[np][2], b[np][3],
                      Bbase + boff[np] + ((c0 ^ b7[np]) << 4));
#pragma unroll
            for (int mi = 0; mi < 4; mi++) {
                uint32_t a0, a1, a2, a3;
                ldmx4(a0, a1, a2, a3, aoff[mi] + ((c0 ^ a7[mi]) << 4));
#pragma unroll
                for (int np = 0; np < 2; np++) {
                    mmafp8(acc[mi][np*2],     a0, a1, a2, a3, b[np][0], b[np][2]);
                    mmafp8(acc[mi][np*2 + 1], a0, a1, a2, a3, b[np][1], b[np][3]);
                }
            }
        }

        int cn0 = cbase + t * 128;
        if (cn0 == rm0) {
#pragma unroll
            for (int mi = 0; mi < 4; mi++)
#pragma unroll
                for (int ni = 0; ni < 4; ni++)
#pragma unroll
                    for (int e = 0; e < 4; e++) {
                        int r = wm + mi * 16 + tq + (e >> 1) * 8;
                        int c = wn + ni * 8 + tc + (e & 1);
                        float v = ex2(acc[mi][ni][e] * LOG2E10);
                        if (r == c) v = 0.0f;
                        rowsum[mi * 2 + (e >> 1)] += v;
                    }
        } else {
#pragma unroll
            for (int mi = 0; mi < 4; mi++)
#pragma unroll
                for (int ni = 0; ni < 4; ni++)
#pragma unroll
                    for (int e = 0; e < 4; e++)
                        rowsum[mi * 2 + (e >> 1)] += ex2(acc[mi][ni][e] * LOG2E10);
        }
    }

    // quad-reduce and accumulate per-row sums
#pragma unroll
    for (int i = 0; i < 8; i++) {
        float s = rowsum[i];
        s += __shfl_xor_sync(0xffffffffu, s, 1);
        s += __shfl_xor_sync(0xffffffffu, s, 2);
        rowsum[i] = s;
    }
    if ((lane & 3) == 0) {
#pragma unroll
        for (int mi = 0; mi < 4; mi++)
#pragma unroll
            for (int h = 0; h < 2; h++)
                atomicAdd(&g_sumexp[rm0 + wm + mi * 16 + h * 8 + tq],
                          rowsum[mi * 2 + h]);
    }

    // completion counting: last CTA of this row-block does the log reduction
    __threadfence();
    __syncthreads();
    if (tid == 0) s_old = atomicAdd(&g_cnt[blockIdx.y], 1);
    __syncthreads();
    if (s_old == (int)gridDim.x - 1) {
        __threadfence();
        float s = 0.0f;
        if (tid < 128) s = lg2(__ldcg(&g_sumexp[rm0 + tid]));
        red[tid < 128 ? tid : 0] = 0.0f;   // init not needed; guarded below
        if (tid < 128) red[tid] = s;
        __syncthreads();
        if (tid < 32) {
            float v = red[tid] + red[tid + 32] + red[tid + 64] + red[tid + 96];
#pragma unroll
            for (int o = 16; o; o >>= 1) v += __shfl_xor_sync(0xffffffffu, v, o);
            if (tid == 0) atomicAdd(&g_lsum, v);
        }
    }
}

// ---------------------------------------------------------------------------
// Kernel 3: final scalar combine
// ---------------------------------------------------------------------------
__global__ void kfinal(float* __restrict__ out)
{
    __shared__ float ps[4];
    int tid = threadIdx.x;               // 128
    float s = 0.0f;
#pragma unroll
    for (int u = 0; u < 4; u++) s += g_posp[tid * 4 + u];
#pragma unroll
    for (int o = 16; o; o >>= 1) s += __shfl_xor_sync(0xffffffffu, s, o);
    if ((tid & 31) == 0) ps[tid >> 5] = s;
    __syncthreads();
    if (tid == 0) {
        const float LN2 = 0.6931471805599453f;
        float pos = ps[0] + ps[1] + ps[2] + ps[3];
        float loss_neg = g_lsum * LN2 / (float)NN + logf(4096.0f / (float)(NN - 1));
        float loss_pos = pos * 10.0f / (float)XROWS;
        out[0] = loss_neg - loss_pos;
    }
}

// ---------------------------------------------------------------------------
extern "C" void kernel_launch(void* const* d_in, const int* in_sizes, int n_in,
                              void* d_out, int out_size)
{
    const float* x  = (const float*)d_in[0];
    const float* xp = (const float*)d_in[1];
    if (n_in >= 2 && in_sizes[0] == BSZ * DN) {
        x  = (const float*)d_in[1];
        xp = (const float*)d_in[0];
    }

    cudaFuncSetAttribute(kmain, cudaFuncAttributeMaxDynamicSharedMemorySize, SMEM_BYTES);

    kprep<<<1088, 256>>>(x, xp);
    dim3 grid(NN / (NTILES * 128), NN / 128);   // (16, 64)
    kmain<<<grid, 256, SMEM_BYTES>>>();
    kfinal<<<1, 128>>>((float*)d_out);
}

// round 5
// speedup vs baseline: 1.2587x; 1.2587x over previous
#include <cuda_runtime.h>
#include <cuda_bf16.h>
#include <math.h>
#include <stdint.h>

// Problem constants
#define NPOS   3
#define BSZ    2048
#define DN     128
#define NN     8192
#define XROWS  (NPOS*BSZ)
#define LOG2E10  14.426950408889634f   // 10 / ln(2)

#define TILE_BYTES 16384               // 128 rows x 128 fp8
#define SMEM_BYTES 32768               // A + B
#define NPAIRS 2080                    // 64*65/2 tile pairs (I<=J)

// Scratch (device globals — no allocation allowed)
__device__ uint8_t g_bZ[NN * DN];      // unit rows, e4m3
__device__ float g_sumexp[NN];
__device__ float g_posp[768];
__device__ float g_lsum;
__device__ int   g_cnt[64];

// ---------------------------------------------------------------- helpers
__device__ __forceinline__ uint32_t s2u(const void* p) {
    uint32_t a;
    asm("{ .reg .u64 t; cvta.to.shared.u64 t, %1; cvt.u32.u64 %0, t; }" : "=r"(a) : "l"(p));
    return a;
}
__device__ __forceinline__ float ex2(float x) {
    float y; asm("ex2.approx.ftz.f32 %0, %1;" : "=f"(y) : "f"(x)); return y;
}
__device__ __forceinline__ float lg2(float x) {
    float y; asm("lg2.approx.f32 %0, %1;" : "=f"(y) : "f"(x)); return y;
}
__device__ __forceinline__ uint16_t cvt8x2(float a, float b) {
    uint16_t r;
    asm("cvt.rn.satfinite.e4m3x2.f32 %0, %1, %2;" : "=h"(r) : "f"(a), "f"(b));
    return r;
}
__device__ __forceinline__ void ldmx4(uint32_t& r0, uint32_t& r1, uint32_t& r2,
                                      uint32_t& r3, uint32_t a) {
    asm volatile("ldmatrix.sync.aligned.m8n8.x4.shared.b16 {%0,%1,%2,%3}, [%4];"
                 : "=r"(r0), "=r"(r1), "=r"(r2), "=r"(r3) : "r"(a));
}
__device__ __forceinline__ void mmafp8(float* d, uint32_t a0, uint32_t a1,
                                       uint32_t a2, uint32_t a3,
                                       uint32_t b0, uint32_t b1) {
    asm volatile(
        "mma.sync.aligned.m16n8k32.row.col.f32.e4m3.e4m3.f32 "
        "{%0,%1,%2,%3},{%4,%5,%6,%7},{%8,%9},{%0,%1,%2,%3};"
        : "+f"(d[0]), "+f"(d[1]), "+f"(d[2]), "+f"(d[3])
        : "r"(a0), "r"(a1), "r"(a2), "r"(a3), "r"(b0), "r"(b1));
}

// Load one 128x128-fp8 tile into smem, XOR-swizzled (chunk c at c^(r&7)).
__device__ __forceinline__ void load_tile(uint32_t sdst, const uint8_t* src,
                                          int row0, int tid) {
#pragma unroll
    for (int i = 0; i < 4; i++) {
        int idx = i * 256 + tid;
        int r = idx >> 3;
        int c = idx & 7;
        uint32_t off = (uint32_t)r * 128u + (uint32_t)((c ^ (r & 7)) << 4);
        const char* g = (const char*)(src + (size_t)(row0 + r) * DN) + (c << 4);
        asm volatile("cp.async.cg.shared.global [%0], [%1], 16;"
                     :: "r"(sdst + off), "l"(g));
    }
}

// ---------------------------------------------------------------------------
// Kernel 1 (prep): blocks 0..1023 normalize rows -> e4m3 (+ zero accums);
// blocks 1024..1791 compute pos partials, ONE (q,b) dot per warp.
// ---------------------------------------------------------------------------
__global__ void kprep(const float* __restrict__ x, const float* __restrict__ xp)
{
    int tid  = threadIdx.x;
    int wid  = tid >> 5;
    int lane = tid & 31;
    int gid  = blockIdx.x * 256 + tid;

    if (gid < NN) g_sumexp[gid] = 0.0f;
    if (gid < 64) g_cnt[gid] = 0;
    if (gid == 64) g_lsum = 0.0f;

    if (blockIdx.x < 1024) {
        int row = gid >> 5;
        const float* src = (row < XROWS) ? (x + (size_t)row * DN)
                                         : (xp + (size_t)(row - XROWS) * DN);
        float4 v = ((const float4*)src)[lane];
        float ss = v.x*v.x + v.y*v.y + v.z*v.z + v.w*v.w;
#pragma unroll
        for (int o = 16; o; o >>= 1) ss += __shfl_xor_sync(0xffffffffu, ss, o);
        float r = rsqrtf(ss);
        uint32_t lo = cvt8x2(v.y * r, v.x * r);
        uint32_t hi = cvt8x2(v.w * r, v.z * r);
        ((uint32_t*)g_bZ)[row * 32 + lane] = (hi << 16) | lo;
    } else {
        __shared__ float wsum[8];
        int pw = (blockIdx.x - 1024) * 8 + wid;   // 0..6143
        int b  = pw & (BSZ - 1);
        int q  = pw >> 11;                         // 0..2
        float4 p = ((const float4*)(xp + (size_t)b * DN))[lane];
        float4 a = ((const float4*)(x + (size_t)(q * BSZ + b) * DN))[lane];
        float ssp = p.x*p.x + p.y*p.y + p.z*p.z + p.w*p.w;
        float ssx = a.x*a.x + a.y*a.y + a.z*a.z + a.w*a.w;
        float dt  = a.x*p.x + a.y*p.y + a.z*p.z + a.w*p.w;
#pragma unroll
        for (int o = 16; o; o >>= 1) {
            ssp += __shfl_xor_sync(0xffffffffu, ssp, o);
            ssx += __shfl_xor_sync(0xffffffffu, ssx, o);
            dt  += __shfl_xor_sync(0xffffffffu, dt,  o);
        }
        if (lane == 0) wsum[wid] = dt * rsqrtf(ssx) * rsqrtf(ssp);
        __syncthreads();
        if (tid == 0) {
            float s = 0.0f;
#pragma unroll
            for (int i = 0; i < 8; i++) s += wsum[i];
            g_posp[blockIdx.x - 1024] = s;
        }
    }
}

// ---------------------------------------------------------------------------
// Kernel 2: symmetric fp8 MMA + exp; each CTA = one tile pair (I<=J).
// Off-diag tiles feed row-sums (block I) AND col-sums (block J).
// Per-row-block counters (64 contributions each) trigger fused log-reduce.
// grid 2080, 256 threads.
// ---------------------------------------------------------------------------
__global__ void __launch_bounds__(256, 2) kmain()
{
    extern __shared__ char smc[];
    __shared__ float red[128];
    __shared__ int soI, soJ;
    uint32_t sb = s2u(smc);
    uint32_t Ab = sb;
    uint32_t Bb = sb + (uint32_t)TILE_BYTES;

    int tid  = threadIdx.x;
    int wid  = tid >> 5;
    int lane = tid & 31;

    // decode pair index -> (I, J), I<=J
    int rem = blockIdx.x, I = 0;
    while (rem >= 64 - I) { rem -= 64 - I; I++; }
    int J = I + rem;
    int rm0 = I * 128, cn0 = J * 128;
    bool diag = (I == J);

    int wm = (wid & 1) * 64;
    int wn = (wid >> 1) * 32;
    int rr = lane & 15;
    int ch = lane >> 4;

    load_tile(Ab, g_bZ, rm0, tid);
    if (!diag) load_tile(Bb, g_bZ, cn0, tid);
    asm volatile("cp.async.commit_group;");

    uint32_t aoff[4]; uint32_t a7[4];
#pragma unroll
    for (int mi = 0; mi < 4; mi++) {
        int row = wm + mi * 16 + rr;
        aoff[mi] = Ab + (uint32_t)row * 128u;
        a7[mi]   = (uint32_t)(row & 7);
    }
    uint32_t Bbase = diag ? Ab : Bb;
    uint32_t boff[2]; uint32_t b7[2];
#pragma unroll
    for (int np = 0; np < 2; np++) {
        int row = wn + np * 16 + rr;
        boff[np] = Bbase + (uint32_t)row * 128u;
        b7[np]   = (uint32_t)(row & 7);
    }

    asm volatile("cp.async.wait_group 0;" ::: "memory");
    __syncthreads();

    float acc[4][4][4];
#pragma unroll
    for (int mi = 0; mi < 4; mi++)
#pragma unroll
        for (int ni = 0; ni < 4; ni++)
#pragma unroll
            for (int e = 0; e < 4; e++) acc[mi][ni][e] = 0.0f;

#pragma unroll
    for (int ks = 0; ks < 4; ks++) {
        uint32_t c0 = (uint32_t)(ks * 2 + ch);
        uint32_t b[2][4];
#pragma unroll
        for (int np = 0; np < 2; np++)
            ldmx4(b[np][0], b[np][1], b[np][2], b[np][3],
                  boff[np] + ((c0 ^ b7[np]) << 4));
#pragma unroll
        for (int mi = 0; mi < 4; mi++) {
            uint32_t a0, a1, a2, a3;
            ldmx4(a0, a1, a2, a3, aoff[mi] + ((c0 ^ a7[mi]) << 4));
#pragma unroll
            for (int np = 0; np < 2; np++) {
                mmafp8(acc[mi][np*2],     a0, a1, a2, a3, b[np][0], b[np][2]);
                mmafp8(acc[mi][np*2 + 1], a0, a1, a2, a3, b[np][1], b[np][3]);
            }
        }
    }

    int tq = lane >> 2;
    int tc = (lane & 3) * 2;
    float rowsum[8], colsum[8];
#pragma unroll
    for (int i = 0; i < 8; i++) { rowsum[i] = 0.0f; colsum[i] = 0.0f; }

    if (diag) {
#pragma unroll
        for (int mi = 0; mi < 4; mi++)
#pragma unroll
            for (int ni = 0; ni < 4; ni++)
#pragma unroll
                for (int e = 0; e < 4; e++) {
                    int r = wm + mi * 16 + tq + (e >> 1) * 8;
                    int c = wn + ni * 8 + tc + (e & 1);
                    float v = ex2(acc[mi][ni][e] * LOG2E10);
                    if (r == c) v = 0.0f;
                    rowsum[mi * 2 + (e >> 1)] += v;
                }
    } else {
#pragma unroll
        for (int mi = 0; mi < 4; mi++)
#pragma unroll
            for (int ni = 0; ni < 4; ni++)
#pragma unroll
                for (int e = 0; e < 4; e++) {
                    float v = ex2(acc[mi][ni][e] * LOG2E10);
                    rowsum[mi * 2 + (e >> 1)] += v;
                    colsum[ni * 2 + (e & 1)]  += v;
                }
    }

    // row sums: quad-reduce, atomics to block I rows
#pragma unroll
    for (int i = 0; i < 8; i++) {
        float s = rowsum[i];
        s += __shfl_xor_sync(0xffffffffu, s, 1);
        s += __shfl_xor_sync(0xffffffffu, s, 2);
        rowsum[i] = s;
    }
    if ((lane & 3) == 0) {
#pragma unroll
        for (int mi = 0; mi < 4; mi++)
#pragma unroll
            for (int h = 0; h < 2; h++)
                atomicAdd(&g_sumexp[rm0 + wm + mi * 16 + h * 8 + tq],
                          rowsum[mi * 2 + h]);
    }

    // col sums (off-diag only): reduce over row-groups, atomics to block J rows
    if (!diag) {
#pragma unroll
        for (int i = 0; i < 8; i++) {
            float s = colsum[i];
            s += __shfl_xor_sync(0xffffffffu, s, 4);
            s += __shfl_xor_sync(0xffffffffu, s, 8);
            s += __shfl_xor_sync(0xffffffffu, s, 16);
            colsum[i] = s;
        }
        if (lane < 4) {
#pragma unroll
            for (int ni = 0; ni < 4; ni++)
#pragma unroll
                for (int par = 0; par < 2; par++)
                    atomicAdd(&g_sumexp[cn0 + wn + ni * 8 + lane * 2 + par],
                              colsum[ni * 2 + par]);
        }
    }

    // completion counting: block K is complete after 64 contributions
    __threadfence();
    __syncthreads();
    if (tid == 0) {
        soI = atomicAdd(&g_cnt[I], 1);
        soJ = diag ? -1 : atomicAdd(&g_cnt[J], 1);
    }
    __syncthreads();

#pragma unroll
    for (int pass = 0; pass < 2; pass++) {
        int blk = pass ? J : I;
        int so  = pass ? soJ : soI;
        if (so == 63) {
            __threadfence();
            if (tid < 128) red[tid] = lg2(__ldcg(&g_sumexp[blk * 128 + tid]));
            __syncthreads();
            if (tid < 32) {
                float v = red[tid] + red[tid + 32] + red[tid + 64] + red[tid + 96];
#pragma unroll
                for (int o = 16; o; o >>= 1) v += __shfl_xor_sync(0xffffffffu, v, o);
                if (tid == 0) atomicAdd(&g_lsum, v);
            }
            __syncthreads();
        }
    }
}

// ---------------------------------------------------------------------------
// Kernel 3: final scalar combine
// ---------------------------------------------------------------------------
__global__ void kfinal(float* __restrict__ out)
{
    __shared__ float ps[4];
    int tid = threadIdx.x;               // 128
    float s = 0.0f;
#pragma unroll
    for (int u = 0; u < 6; u++) s += g_posp[tid + u * 128];
#pragma unroll
    for (int o = 16; o; o >>= 1) s += __shfl_xor_sync(0xffffffffu, s, o);
    if ((tid & 31) == 0) ps[tid >> 5] = s;
    __syncthreads();
    if (tid == 0) {
        const float LN2 = 0.6931471805599453f;
        float pos = ps[0] + ps[1] + ps[2] + ps[3];
        float loss_neg = g_lsum * LN2 / (float)NN + logf(4096.0f / (float)(NN - 1));
        float loss_pos = pos * 10.0f / (float)XROWS;
        out[0] = loss_neg - loss_pos;
    }
}

// ---------------------------------------------------------------------------
extern "C" void kernel_launch(void* const* d_in, const int* in_sizes, int n_in,
                              void* d_out, int out_size)
{
    const float* x  = (const float*)d_in[0];
    const float* xp = (const float*)d_in[1];
    if (n_in >= 2 && in_sizes[0] == BSZ * DN) {
        x  = (const float*)d_in[1];
        xp = (const float*)d_in[0];
    }

    cudaFuncSetAttribute(kmain, cudaFuncAttributeMaxDynamicSharedMemorySize, SMEM_BYTES);

    kprep<<<1792, 256>>>(x, xp);
    kmain<<<NPAIRS, 256, SMEM_BYTES>>>();
    kfinal<<<1, 128>>>((float*)d_out);
}

// round 6
// speedup vs baseline: 1.3698x; 1.0883x over previous
#include <cuda_runtime.h>
#include <cuda_bf16.h>
#include <math.h>
#include <stdint.h>

// Problem constants
#define NPOS   3
#define BSZ    2048
#define DN     128
#define NN     8192
#define XROWS  (NPOS*BSZ)
#define LOG2E10  14.426950408889634f   // 10 / ln(2)

#define TILE_BYTES 16384               // 128 rows x 128 fp8
#define SMEM_BYTES 49152               // A + 2xB

// Scratch (device globals — no allocation allowed)
__device__ uint8_t g_bA[NN * DN];      // unit rows * (10/ln2), e4m3
__device__ uint8_t g_bZ[NN * DN];      // unit rows, e4m3
__device__ float g_sumexp[NN];
__device__ float g_posp[768];
__device__ float g_lsum;
__device__ int   g_cnt[64];

// ---------------------------------------------------------------- helpers
__device__ __forceinline__ uint32_t s2u(const void* p) {
    uint32_t a;
    asm("{ .reg .u64 t; cvta.to.shared.u64 t, %1; cvt.u32.u64 %0, t; }" : "=r"(a) : "l"(p));
    return a;
}
__device__ __forceinline__ float ex2(float x) {
    float y; asm("ex2.approx.ftz.f32 %0, %1;" : "=f"(y) : "f"(x)); return y;
}
__device__ __forceinline__ float lg2(float x) {
    float y; asm("lg2.approx.f32 %0, %1;" : "=f"(y) : "f"(x)); return y;
}
__device__ __forceinline__ uint16_t cvt8x2(float a, float b) {
    uint16_t r;
    asm("cvt.rn.satfinite.e4m3x2.f32 %0, %1, %2;" : "=h"(r) : "f"(a), "f"(b));
    return r;
}
__device__ __forceinline__ void ldmx4(uint32_t& r0, uint32_t& r1, uint32_t& r2,
                                      uint32_t& r3, uint32_t a) {
    asm volatile("ldmatrix.sync.aligned.m8n8.x4.shared.b16 {%0,%1,%2,%3}, [%4];"
                 : "=r"(r0), "=r"(r1), "=r"(r2), "=r"(r3) : "r"(a));
}
__device__ __forceinline__ void mmafp8(float* d, uint32_t a0, uint32_t a1,
                                       uint32_t a2, uint32_t a3,
                                       uint32_t b0, uint32_t b1) {
    asm volatile(
        "mma.sync.aligned.m16n8k32.row.col.f32.e4m3.e4m3.f32 "
        "{%0,%1,%2,%3},{%4,%5,%6,%7},{%8,%9},{%0,%1,%2,%3};"
        : "+f"(d[0]), "+f"(d[1]), "+f"(d[2]), "+f"(d[3])
        : "r"(a0), "r"(a1), "r"(a2), "r"(a3), "r"(b0), "r"(b1));
}

// Load one 128x128-fp8 tile into smem, XOR-swizzled (chunk c at c^(r&7)).
__device__ __forceinline__ void load_tile(uint32_t sdst, const uint8_t* src,
                                          int row0, int tid) {
#pragma unroll
    for (int i = 0; i < 4; i++) {
        int idx = i * 256 + tid;
        int r = idx >> 3;
        int c = idx & 7;
        uint32_t off = (uint32_t)r * 128u + (uint32_t)((c ^ (r & 7)) << 4);
        const char* g = (const char*)(src + (size_t)(row0 + r) * DN) + (c << 4);
        asm volatile("cp.async.cg.shared.global [%0], [%1], 16;"
                     :: "r"(sdst + off), "l"(g));
    }
}

// ---------------------------------------------------------------------------
// Kernel 1 (prep): blocks 0..511 normalize rows -> e4m3 (scaled + unscaled,
// 2 rows/warp for MLP); blocks 512..1279 pos partials (one (q,b) per warp).
// ---------------------------------------------------------------------------
__global__ void kprep(const float* __restrict__ x, const float* __restrict__ xp)
{
    int tid  = threadIdx.x;
    int wid  = tid >> 5;
    int lane = tid & 31;
    int gid  = blockIdx.x * 256 + tid;

    if (gid < NN) g_sumexp[gid] = 0.0f;
    if (gid < 64) g_cnt[gid] = 0;
    if (gid == 64) g_lsum = 0.0f;

    if (blockIdx.x < 512) {
        int row0 = blockIdx.x * 16 + wid * 2;
#pragma unroll
        for (int u = 0; u < 2; u++) {
            int row = row0 + u;
            const float* src = (row < XROWS) ? (x + (size_t)row * DN)
                                             : (xp + (size_t)(row - XROWS) * DN);
            float4 v = ((const float4*)src)[lane];
            float ss = v.x*v.x + v.y*v.y + v.z*v.z + v.w*v.w;
#pragma unroll
            for (int o = 16; o; o >>= 1) ss += __shfl_xor_sync(0xffffffffu, ss, o);
            float r = rsqrtf(ss);
            float bx = v.x * r, by = v.y * r, bz = v.z * r, bw = v.w * r;
            uint32_t lo = cvt8x2(by, bx);
            uint32_t hi = cvt8x2(bw, bz);
            ((uint32_t*)g_bZ)[row * 32 + lane] = (hi << 16) | lo;
            float s = LOG2E10;
            lo = cvt8x2(by * s, bx * s);
            hi = cvt8x2(bw * s, bz * s);
            ((uint32_t*)g_bA)[row * 32 + lane] = (hi << 16) | lo;
        }
    } else {
        __shared__ float wsum[8];
        int pw = (blockIdx.x - 512) * 8 + wid;     // 0..6143
        int b  = pw & (BSZ - 1);
        int q  = pw >> 11;                          // 0..2
        float4 p = ((const float4*)(xp + (size_t)b * DN))[lane];
        float4 a = ((const float4*)(x + (size_t)(q * BSZ + b) * DN))[lane];
        float ssp = p.x*p.x + p.y*p.y + p.z*p.z + p.w*p.w;
        float ssx = a.x*a.x + a.y*a.y + a.z*a.z + a.w*a.w;
        float dt  = a.x*p.x + a.y*p.y + a.z*p.z + a.w*p.w;
#pragma unroll
        for (int o = 16; o; o >>= 1) {
            ssp += __shfl_xor_sync(0xffffffffu, ssp, o);
            ssx += __shfl_xor_sync(0xffffffffu, ssx, o);
            dt  += __shfl_xor_sync(0xffffffffu, dt,  o);
        }
        if (lane == 0) wsum[wid] = dt * rsqrtf(ssx) * rsqrtf(ssp);
        __syncthreads();
        if (tid == 0) {
            float s = 0.0f;
#pragma unroll
            for (int i = 0; i < 8; i++) s += wsum[i];
            g_posp[blockIdx.x - 512] = s;
        }
    }
}

// ---------------------------------------------------------------------------
// Kernel 2: symmetric fp8 MMA + exp, strip form.
// CTA (I, strip): tiles (I, J=(I+k)&63), k = strip*4 .. +3 (+k=32 if strip==7
// and I<32). A (scaled) resident; B double-buffered. Row sums accumulate in
// registers across the strip. grid 512, 256 threads.
// ---------------------------------------------------------------------------
__global__ void __launch_bounds__(256, 2) kmain()
{
    extern __shared__ char smc[];
    __shared__ float red[128];
    __shared__ int olds[6];
    uint32_t sb = s2u(smc);
    uint32_t Ab = sb;
    uint32_t Bb = sb + (uint32_t)TILE_BYTES;

    int tid  = threadIdx.x;
    int wid  = tid >> 5;
    int lane = tid & 31;

    int I     = blockIdx.x >> 3;
    int strip = blockIdx.x & 7;
    int k0    = strip * 4;
    int nt    = (strip == 7 && I < 32) ? 5 : 4;
    int rm0   = I * 128;

    int wm = (wid & 1) * 64;
    int wn = (wid >> 1) * 32;
    int rr = lane & 15;
    int ch = lane >> 4;

    load_tile(Ab, g_bA, rm0, tid);
    load_tile(Bb, g_bZ, ((I + k0) & 63) * 128, tid);
    asm volatile("cp.async.commit_group;");

    uint32_t aoff[4]; uint32_t a7[4];
#pragma unroll
    for (int mi = 0; mi < 4; mi++) {
        int row = wm + mi * 16 + rr;
        aoff[mi] = Ab + (uint32_t)row * 128u;
        a7[mi]   = (uint32_t)(row & 7);
    }
    uint32_t boff[2]; uint32_t b7[2];
#pragma unroll
    for (int np = 0; np < 2; np++) {
        int row = wn + np * 16 + rr;
        boff[np] = (uint32_t)row * 128u;
        b7[np]   = (uint32_t)(row & 7);
    }

    float rowsum[8];
#pragma unroll
    for (int i = 0; i < 8; i++) rowsum[i] = 0.0f;

    int tq = lane >> 2;
    int tc = (lane & 3) * 2;

    for (int t = 0; t < nt; t++) {
        int buf = t & 1;
        __syncthreads();                     // buf^1 free
        if (t + 1 < nt) {
            load_tile(Bb + (uint32_t)(buf ^ 1) * TILE_BYTES, g_bZ,
                      ((I + k0 + t + 1) & 63) * 128, tid);
            asm volatile("cp.async.commit_group;");
            asm volatile("cp.async.wait_group 1;" ::: "memory");
        } else {
            asm volatile("cp.async.wait_group 0;" ::: "memory");
        }
        __syncthreads();

        uint32_t Bbase = Bb + (uint32_t)buf * TILE_BYTES;

        float acc[4][4][4];
#pragma unroll
        for (int mi = 0; mi < 4; mi++)
#pragma unroll
            for (int ni = 0; ni < 4; ni++)
#pragma unroll
                for (int e = 0; e < 4; e++) acc[mi][ni][e] = 0.0f;

#pragma unroll
        for (int ks = 0; ks < 4; ks++) {
            uint32_t c0 = (uint32_t)(ks * 2 + ch);
            uint32_t b[2][4];
#pragma unroll
            for (int np = 0; np < 2; np++)
                ldmx4(b[np][0], b[np][1], b[np][2], b[np][3],
                      Bbase + boff[np] + ((c0 ^ b7[np]) << 4));
#pragma unroll
            for (int mi = 0; mi < 4; mi++) {
                uint32_t a0, a1, a2, a3;
                ldmx4(a0, a1, a2, a3, aoff[mi] + ((c0 ^ a7[mi]) << 4));
#pragma unroll
                for (int np = 0; np < 2; np++) {
                    mmafp8(acc[mi][np*2],     a0, a1, a2, a3, b[np][0], b[np][2]);
                    mmafp8(acc[mi][np*2 + 1], a0, a1, a2, a3, b[np][1], b[np][3]);
                }
            }
        }

        bool diag = (k0 + t) == 0;
        float colsum[8];
#pragma unroll
        for (int i = 0; i < 8; i++) colsum[i] = 0.0f;

        if (diag) {
#pragma unroll
            for (int mi = 0; mi < 4; mi++)
#pragma unroll
                for (int ni = 0; ni < 4; ni++)
#pragma unroll
                    for (int e = 0; e < 4; e++) {
                        int r = wm + mi * 16 + tq + (e >> 1) * 8;
                        int c = wn + ni * 8 + tc + (e & 1);
                        float v = ex2(acc[mi][ni][e]);
                        if (r == c) v = 0.0f;
                        rowsum[mi * 2 + (e >> 1)] += v;
                    }
        } else {
#pragma unroll
            for (int mi = 0; mi < 4; mi++)
#pragma unroll
                for (int ni = 0; ni < 4; ni++)
#pragma unroll
                    for (int e = 0; e < 4; e++) {
                        float v = ex2(acc[mi][ni][e]);
                        rowsum[mi * 2 + (e >> 1)] += v;
                        colsum[ni * 2 + (e & 1)]  += v;
                    }
            // col sums -> block J rows
#pragma unroll
            for (int i = 0; i < 8; i++) {
                float s = colsum[i];
                s += __shfl_xor_sync(0xffffffffu, s, 4);
                s += __shfl_xor_sync(0xffffffffu, s, 8);
                s += __shfl_xor_sync(0xffffffffu, s, 16);
                colsum[i] = s;
            }
            if (lane < 4) {
                int cn0 = ((I + k0 + t) & 63) * 128;
#pragma unroll
                for (int ni = 0; ni < 4; ni++)
#pragma unroll
                    for (int par = 0; par < 2; par++)
                        atomicAdd(&g_sumexp[cn0 + wn + ni * 8 + lane * 2 + par],
                                  colsum[ni * 2 + par]);
            }
        }
    }

    // row sums (accumulated across strip): quad-reduce + atomics
#pragma unroll
    for (int i = 0; i < 8; i++) {
        float s = rowsum[i];
        s += __shfl_xor_sync(0xffffffffu, s, 1);
        s += __shfl_xor_sync(0xffffffffu, s, 2);
        rowsum[i] = s;
    }
    if ((lane & 3) == 0) {
#pragma unroll
        for (int mi = 0; mi < 4; mi++)
#pragma unroll
            for (int h = 0; h < 2; h++)
                atomicAdd(&g_sumexp[rm0 + wm + mi * 16 + h * 8 + tq],
                          rowsum[mi * 2 + h]);
    }

    // completion counters: rows of I (once) + cols of each off-diag J.
    // total contributions per block = 39 + (blk >= 32)
    __threadfence();
    __syncthreads();
    if (tid == 0) {
        olds[0] = atomicAdd(&g_cnt[I], 1);
        for (int t = 0; t < nt; t++)
            olds[1 + t] = (k0 + t == 0) ? -2
                        : atomicAdd(&g_cnt[(I + k0 + t) & 63], 1);
    }
    __syncthreads();

    for (int s = 0; s <= nt; s++) {
        int blk = (s == 0) ? I : ((I + k0 + s - 1) & 63);
        int tot = 39 + (blk >= 32 ? 1 : 0);
        if (olds[s] == tot - 1) {
            __threadfence();
            if (tid < 128) red[tid] = lg2(__ldcg(&g_sumexp[blk * 128 + tid]));
            __syncthreads();
            if (tid < 32) {
                float v = red[tid] + red[tid + 32] + red[tid + 64] + red[tid + 96];
#pragma unroll
                for (int o = 16; o; o >>= 1) v += __shfl_xor_sync(0xffffffffu, v, o);
                if (tid == 0) atomicAdd(&g_lsum, v);
            }
            __syncthreads();
        }
    }
}

// ---------------------------------------------------------------------------
// Kernel 3: final scalar combine
// ---------------------------------------------------------------------------
__global__ void kfinal(float* __restrict__ out)
{
    __shared__ float ps[4];
    int tid = threadIdx.x;               // 128
    float s = 0.0f;
#pragma unroll
    for (int u = 0; u < 6; u++) s += g_posp[tid + u * 128];
#pragma unroll
    for (int o = 16; o; o >>= 1) s += __shfl_xor_sync(0xffffffffu, s, o);
    if ((tid & 31) == 0) ps[tid >> 5] = s;
    __syncthreads();
    if (tid == 0) {
        const float LN2 = 0.6931471805599453f;
        float pos = ps[0] + ps[1] + ps[2] + ps[3];
        float loss_neg = g_lsum * LN2 / (float)NN + logf(4096.0f / (float)(NN - 1));
        float loss_pos = pos * 10.0f / (float)XROWS;
        out[0] = loss_neg - loss_pos;
    }
}

// ---------------------------------------------------------------------------
extern "C" void kernel_launch(void* const* d_in, const int* in_sizes, int n_in,
                              void* d_out, int out_size)
{
    const float* x  = (const float*)d_in[0];
    const float* xp = (const float*)d_in[1];
    if (n_in >= 2 && in_sizes[0] == BSZ * DN) {
        x  = (const float*)d_in[1];
        xp = (const float*)d_in[0];
    }

    cudaFuncSetAttribute(kmain, cudaFuncAttributeMaxDynamicSharedMemorySize, SMEM_BYTES);

    kprep<<<1280, 256>>>(x, xp);
    kmain<<<512, 256, SMEM_BYTES>>>();
    kfinal<<<1, 128>>>((float*)d_out);
}

// round 7
// speedup vs baseline: 1.5973x; 1.1660x over previous
#include <cuda_runtime.h>
#include <cuda_bf16.h>
#include <math.h>
#include <stdint.h>

// Problem constants
#define NPOS   3
#define BSZ    2048
#define DN     128
#define NN     8192
#define XROWS  (NPOS*BSZ)
#define LOG2E10  14.426950408889634f   // 10 / ln(2)

#define TILE_BYTES 16384               // 128 rows x 128 fp8
#define PAIR_BYTES 32768               // A + B
#define SMEM_BYTES 65536               // double-buffered pairs
#define NTILE 2080                     // 64 diag + 2016 off-diag
#define NCTA  592                      // 2 CTAs/SM x 148 SMs x 2 waves

// Scratch (device globals — no allocation allowed)
__device__ uint8_t g_bA[NN * DN];      // unit rows * (10/ln2), e4m3
__device__ uint8_t g_bZ[NN * DN];      // unit rows, e4m3
__device__ float g_sumexp[NN];
__device__ float g_posp[768];
__device__ float g_lsum;
__device__ float g_posT;
__device__ int   g_done;

// ---------------------------------------------------------------- helpers
__device__ __forceinline__ uint32_t s2u(const void* p) {
    uint32_t a;
    asm("{ .reg .u64 t; cvta.to.shared.u64 t, %1; cvt.u32.u64 %0, t; }" : "=r"(a) : "l"(p));
    return a;
}
__device__ __forceinline__ float ex2(float x) {
    float y; asm("ex2.approx.ftz.f32 %0, %1;" : "=f"(y) : "f"(x)); return y;
}
__device__ __forceinline__ float lg2(float x) {
    float y; asm("lg2.approx.f32 %0, %1;" : "=f"(y) : "f"(x)); return y;
}
__device__ __forceinline__ uint16_t cvt8x2(float a, float b) {
    uint16_t r;
    asm("cvt.rn.satfinite.e4m3x2.f32 %0, %1, %2;" : "=h"(r) : "f"(a), "f"(b));
    return r;
}
__device__ __forceinline__ void ldmx4(uint32_t& r0, uint32_t& r1, uint32_t& r2,
                                      uint32_t& r3, uint32_t a) {
    asm volatile("ldmatrix.sync.aligned.m8n8.x4.shared.b16 {%0,%1,%2,%3}, [%4];"
                 : "=r"(r0), "=r"(r1), "=r"(r2), "=r"(r3) : "r"(a));
}
__device__ __forceinline__ void mmafp8(float* d, uint32_t a0, uint32_t a1,
                                       uint32_t a2, uint32_t a3,
                                       uint32_t b0, uint32_t b1) {
    asm volatile(
        "mma.sync.aligned.m16n8k32.row.col.f32.e4m3.e4m3.f32 "
        "{%0,%1,%2,%3},{%4,%5,%6,%7},{%8,%9},{%0,%1,%2,%3};"
        : "+f"(d[0]), "+f"(d[1]), "+f"(d[2]), "+f"(d[3])
        : "r"(a0), "r"(a1), "r"(a2), "r"(a3), "r"(b0), "r"(b1));
}

// decode flattened tile index -> (I, J)
__device__ __forceinline__ void decode(int g, int& I, int& J) {
    if (g < 33 * 32) { I = g / 33; J = (I + (g - I * 33)) & 63; }
    else { int h = g - 33 * 32; I = 32 + h / 32; J = (I + (h - (I - 32) * 32)) & 63; }
}

// Load one 128x128-fp8 tile into smem, XOR-swizzled (chunk c at c^(r&7)).
__device__ __forceinline__ void load_tile(uint32_t sdst, const uint8_t* src,
                                          int row0, int tid) {
#pragma unroll
    for (int i = 0; i < 4; i++) {
        int idx = i * 256 + tid;
        int r = idx >> 3;
        int c = idx & 7;
        uint32_t off = (uint32_t)r * 128u + (uint32_t)((c ^ (r & 7)) << 4);
        const char* g = (const char*)(src + (size_t)(row0 + r) * DN) + (c << 4);
        asm volatile("cp.async.cg.shared.global [%0], [%1], 16;"
                     :: "r"(sdst + off), "l"(g));
    }
}

// ---------------------------------------------------------------------------
// Kernel 1 (prep): blocks 0..511 normalize rows -> e4m3 (scaled + unscaled,
// 2 rows/warp, loads batched); blocks 512..1279 pos partials (1 dot/warp).
// ---------------------------------------------------------------------------
__global__ void kprep(const float* __restrict__ x, const float* __restrict__ xp)
{
    int tid  = threadIdx.x;
    int wid  = tid >> 5;
    int lane = tid & 31;
    int gid  = blockIdx.x * 256 + tid;

    if (gid < NN) g_sumexp[gid] = 0.0f;
    if (gid == 0) { g_lsum = 0.0f; g_posT = 0.0f; g_done = 0; }

    if (blockIdx.x < 512) {
        int row0 = blockIdx.x * 16 + wid * 2;
        const float* s0 = (row0 < XROWS) ? (x + (size_t)row0 * DN)
                                         : (xp + (size_t)(row0 - XROWS) * DN);
        const float* s1 = (row0 + 1 < XROWS) ? (x + (size_t)(row0 + 1) * DN)
                                             : (xp + (size_t)(row0 + 1 - XROWS) * DN);
        float4 v0 = ((const float4*)s0)[lane];
        float4 v1 = ((const float4*)s1)[lane];
        float ss0 = v0.x*v0.x + v0.y*v0.y + v0.z*v0.z + v0.w*v0.w;
        float ss1 = v1.x*v1.x + v1.y*v1.y + v1.z*v1.z + v1.w*v1.w;
#pragma unroll
        for (int o = 16; o; o >>= 1) {
            ss0 += __shfl_xor_sync(0xffffffffu, ss0, o);
            ss1 += __shfl_xor_sync(0xffffffffu, ss1, o);
        }
        float r0 = rsqrtf(ss0), r1 = rsqrtf(ss1);
        {
            float bx = v0.x*r0, by = v0.y*r0, bz = v0.z*r0, bw = v0.w*r0;
            ((uint32_t*)g_bZ)[row0 * 32 + lane] =
                ((uint32_t)cvt8x2(bw, bz) << 16) | cvt8x2(by, bx);
            ((uint32_t*)g_bA)[row0 * 32 + lane] =
                ((uint32_t)cvt8x2(bw*LOG2E10, bz*LOG2E10) << 16) | cvt8x2(by*LOG2E10, bx*LOG2E10);
        }
        {
            float bx = v1.x*r1, by = v1.y*r1, bz = v1.z*r1, bw = v1.w*r1;
            ((uint32_t*)g_bZ)[(row0 + 1) * 32 + lane] =
                ((uint32_t)cvt8x2(bw, bz) << 16) | cvt8x2(by, bx);
            ((uint32_t*)g_bA)[(row0 + 1) * 32 + lane] =
                ((uint32_t)cvt8x2(bw*LOG2E10, bz*LOG2E10) << 16) | cvt8x2(by*LOG2E10, bx*LOG2E10);
        }
    } else {
        __shared__ float wsum[8];
        int pw = (blockIdx.x - 512) * 8 + wid;     // 0..6143
        int b  = pw & (BSZ - 1);
        int q  = pw >> 11;                          // 0..2
        float4 p = ((const float4*)(xp + (size_t)b * DN))[lane];
        float4 a = ((const float4*)(x + (size_t)(q * BSZ + b) * DN))[lane];
        float ssp = p.x*p.x + p.y*p.y + p.z*p.z + p.w*p.w;
        float ssx = a.x*a.x + a.y*a.y + a.z*a.z + a.w*a.w;
        float dt  = a.x*p.x + a.y*p.y + a.z*p.z + a.w*p.w;
#pragma unroll
        for (int o = 16; o; o >>= 1) {
            ssp += __shfl_xor_sync(0xffffffffu, ssp, o);
            ssx += __shfl_xor_sync(0xffffffffu, ssx, o);
            dt  += __shfl_xor_sync(0xffffffffu, dt,  o);
        }
        if (lane == 0) wsum[wid] = dt * rsqrtf(ssx) * rsqrtf(ssp);
        __syncthreads();
        if (tid == 0) {
            float s = 0.0f;
#pragma unroll
            for (int i = 0; i < 8; i++) s += wsum[i];
            g_posp[blockIdx.x - 512] = s;
        }
    }
}

// ---------------------------------------------------------------------------
// Kernel 2: symmetric fp8 MMA + exp, flattened balanced tiles.
// CTA c: tiles [c*2080/592, (c+1)*2080/592) — 3 or 4 tiles. (A,B) pairs
// double-buffered; row sums in registers, flushed on I change.
// grid 592, 256 threads, 64KB smem.
// ---------------------------------------------------------------------------
__global__ void __launch_bounds__(256, 2) kmain()
{
    extern __shared__ char smc[];
    uint32_t sb = s2u(smc);

    int tid  = threadIdx.x;
    int wid  = tid >> 5;
    int lane = tid & 31;

    int g0 = (blockIdx.x * NTILE) / NCTA;
    int g1 = ((blockIdx.x + 1) * NTILE) / NCTA;

    int wm = (wid & 1) * 64;
    int wn = (wid >> 1) * 32;
    int rr = lane & 15;
    int ch = lane >> 4;

    // per-warp fragment row offsets (relative to buffer base)
    uint32_t arow[4]; uint32_t a7[4];
#pragma unroll
    for (int mi = 0; mi < 4; mi++) {
        int row = wm + mi * 16 + rr;
        arow[mi] = (uint32_t)row * 128u;
        a7[mi]   = (uint32_t)(row & 7);
    }
    uint32_t brow[2]; uint32_t b7[2];
#pragma unroll
    for (int np = 0; np < 2; np++) {
        int row = wn + np * 16 + rr;
        brow[np] = (uint32_t)row * 128u;
        b7[np]   = (uint32_t)(row & 7);
    }

    int I, J;
    decode(g0, I, J);
    load_tile(sb, g_bA, I * 128, tid);
    load_tile(sb + TILE_BYTES, g_bZ, J * 128, tid);
    asm volatile("cp.async.commit_group;");

    float rowsum[8];
#pragma unroll
    for (int i = 0; i < 8; i++) rowsum[i] = 0.0f;

    int tq = lane >> 2;
    int tc = (lane & 3) * 2;

    for (int t = g0; t < g1; t++) {
        int buf = (t - g0) & 1;
        int In = -1, Jn = -1;
        __syncthreads();                     // all warps done with buf^1
        if (t + 1 < g1) {
            decode(t + 1, In, Jn);
            uint32_t dst = sb + (uint32_t)(buf ^ 1) * PAIR_BYTES;
            load_tile(dst, g_bA, In * 128, tid);
            load_tile(dst + TILE_BYTES, g_bZ, Jn * 128, tid);
            asm volatile("cp.async.commit_group;");
            asm volatile("cp.async.wait_group 1;" ::: "memory");
        } else {
            asm volatile("cp.async.wait_group 0;" ::: "memory");
        }
        __syncthreads();

        uint32_t Abase = sb + (uint32_t)buf * PAIR_BYTES;
        uint32_t Bbase = Abase + TILE_BYTES;

        float acc[4][4][4];
#pragma unroll
        for (int mi = 0; mi < 4; mi++)
#pragma unroll
            for (int ni = 0; ni < 4; ni++)
#pragma unroll
                for (int e = 0; e < 4; e++) acc[mi][ni][e] = 0.0f;

#pragma unroll
        for (int ks = 0; ks < 4; ks++) {
            uint32_t c0 = (uint32_t)(ks * 2 + ch);
            uint32_t b[2][4];
#pragma unroll
            for (int np = 0; np < 2; np++)
                ldmx4(b[np][0], b[np][1], b[np][2], b[np][3],
                      Bbase + brow[np] + ((c0 ^ b7[np]) << 4));
#pragma unroll
            for (int mi = 0; mi < 4; mi++) {
                uint32_t a0, a1, a2, a3;
                ldmx4(a0, a1, a2, a3, Abase + arow[mi] + ((c0 ^ a7[mi]) << 4));
#pragma unroll
                for (int np = 0; np < 2; np++) {
                    mmafp8(acc[mi][np*2],     a0, a1, a2, a3, b[np][0], b[np][2]);
                    mmafp8(acc[mi][np*2 + 1], a0, a1, a2, a3, b[np][1], b[np][3]);
                }
            }
        }

        if (I == J) {
            // diagonal tile: rows only, skip r==c
#pragma unroll
            for (int mi = 0; mi < 4; mi++)
#pragma unroll
                for (int ni = 0; ni < 4; ni++)
#pragma unroll
                    for (int e = 0; e < 4; e++) {
                        int r = wm + mi * 16 + tq + (e >> 1) * 8;
                        int c = wn + ni * 8 + tc + (e & 1);
                        float v = ex2(acc[mi][ni][e]);
                        if (r == c) v = 0.0f;
                        rowsum[mi * 2 + (e >> 1)] += v;
                    }
        } else {
            float colsum[8];
#pragma unroll
            for (int i = 0; i < 8; i++) colsum[i] = 0.0f;
#pragma unroll
            for (int mi = 0; mi < 4; mi++)
#pragma unroll
                for (int ni = 0; ni < 4; ni++)
#pragma unroll
                    for (int e = 0; e < 4; e++) {
                        float v = ex2(acc[mi][ni][e]);
                        rowsum[mi * 2 + (e >> 1)] += v;
                        colsum[ni * 2 + (e & 1)]  += v;
                    }
            // col sums -> block J rows
#pragma unroll
            for (int i = 0; i < 8; i++) {
                float s = colsum[i];
                s += __shfl_xor_sync(0xffffffffu, s, 4);
                s += __shfl_xor_sync(0xffffffffu, s, 8);
                s += __shfl_xor_sync(0xffffffffu, s, 16);
                colsum[i] = s;
            }
            if (lane < 4) {
#pragma unroll
                for (int ni = 0; ni < 4; ni++)
#pragma unroll
                    for (int par = 0; par < 2; par++)
                        atomicAdd(&g_sumexp[J * 128 + wn + ni * 8 + lane * 2 + par],
                                  colsum[ni * 2 + par]);
            }
        }

        // flush row sums when I changes (or last tile)
        if (t + 1 >= g1 || In != I) {
            float rs[8];
#pragma unroll
            for (int i = 0; i < 8; i++) {
                float s = rowsum[i];
                s += __shfl_xor_sync(0xffffffffu, s, 1);
                s += __shfl_xor_sync(0xffffffffu, s, 2);
                rs[i] = s;
                rowsum[i] = 0.0f;
            }
            if ((lane & 3) == 0) {
#pragma unroll
                for (int mi = 0; mi < 4; mi++)
#pragma unroll
                    for (int h = 0; h < 2; h++)
                        atomicAdd(&g_sumexp[I * 128 + wm + mi * 16 + h * 8 + tq],
                                  rs[mi * 2 + h]);
            }
        }
        I = In; J = Jn;
    }
}

// ---------------------------------------------------------------------------
// Kernel 3: log-reduce + pos combine. grid 64 x 128 threads.
// ---------------------------------------------------------------------------
__global__ void kfinal(float* __restrict__ out)
{
    __shared__ float rs[4], rp[4];
    int tid = threadIdx.x;
    int b   = blockIdx.x;

    float s = lg2(g_sumexp[b * 128 + tid]);
    float p = (tid < 12) ? g_posp[b * 12 + tid] : 0.0f;
#pragma unroll
    for (int o = 16; o; o >>= 1) {
        s += __shfl_xor_sync(0xffffffffu, s, o);
        p += __shfl_xor_sync(0xffffffffu, p, o);
    }
    if ((tid & 31) == 0) { rs[tid >> 5] = s; rp[tid >> 5] = p; }
    __syncthreads();
    if (tid == 0) {
        float sb = rs[0] + rs[1] + rs[2] + rs[3];
        float pb = rp[0] + rp[1] + rp[2] + rp[3];
        atomicAdd(&g_lsum, sb);
        atomicAdd(&g_posT, pb);
        __threadfence();
        int old = atomicAdd(&g_done, 1);
        if (old == 63) {
            const float LN2 = 0.6931471805599453f;
            float L = atomicAdd(&g_lsum, 0.0f);
            float P = atomicAdd(&g_posT, 0.0f);
            float loss_neg = L * LN2 / (float)NN + logf(4096.0f / (float)(NN - 1));
            float loss_pos = P * 10.0f / (float)XROWS;
            out[0] = loss_neg - loss_pos;
        }
    }
}

// ---------------------------------------------------------------------------
extern "C" void kernel_launch(void* const* d_in, const int* in_sizes, int n_in,
                              void* d_out, int out_size)
{
    const float* x  = (const float*)d_in[0];
    const float* xp = (const float*)d_in[1];
    if (n_in >= 2 && in_sizes[0] == BSZ * DN) {
        x  = (const float*)d_in[1];
        xp = (const float*)d_in[0];
    }

    cudaFuncSetAttribute(kmain, cudaFuncAttributeMaxDynamicSharedMemorySize, SMEM_BYTES);

    kprep<<<1280, 256>>>(x, xp);
    kmain<<<NCTA, 256, SMEM_BYTES>>>();
    kfinal<<<64, 128>>>((float*)d_out);
}